// round 2
// baseline (speedup 1.0000x reference)
#include <cuda_runtime.h>

#define B_  4
#define K_  16
#define H_  480
#define W_  640
#define HW_ (H_*W_)
#define P_  200000

// Pre-packed point-cloud features: one aligned 16B row per point -> exactly one
// 32B L2 sector per gather (the minimum possible).
__device__ float4 g_tab[P_];

__global__ void prep_kernel(const float* __restrict__ pt) {
    int i = blockIdx.x * blockDim.x + threadIdx.x;
    if (i < P_) {
        g_tab[i] = make_float4(pt[i], pt[P_ + i], pt[2 * P_ + i], 0.f);
    }
}

__global__ void __launch_bounds__(256) composite_kernel(
    const int*   __restrict__ frag,   // int32 (JAX demotes int64 without x64 mode)
    const float* __restrict__ alpha,
    const float* __restrict__ im,
    float*       __restrict__ out)
{
    int p = blockIdx.x * blockDim.x + threadIdx.x;  // pixel index within a batch image
    if (p >= HW_) return;
    int b = blockIdx.y;
    size_t base = (size_t)b * K_ * HW_ + p;

    // Layer 0 decides background: if frag0 < 0 the whole composite is replaced by im.
    int f0 = frag[base];
    size_t ob = (size_t)b * 3 * HW_ + p;
    if (f0 < 0) {
        out[ob          ] = im[p          ];
        out[ob +     HW_] = im[p +     HW_];
        out[ob + 2 * HW_] = im[p + 2 * HW_];
        return;
    }

    float T = 1.f, c0 = 0.f, c1 = 0.f, c2 = 0.f;
    #pragma unroll
    for (int k = 0; k < K_; k++) {
        size_t off = base + (size_t)k * HW_;
        int   f  = (k == 0) ? f0 : frag[off];
        float al = alpha[off];
        if (f >= 0) {                 // invalid fragment => weight exactly 0: skip gather
            float w = al * T;
            float4 ft = __ldg(&g_tab[f]);
            c0 = fmaf(w, ft.x, c0);
            c1 = fmaf(w, ft.y, c1);
            c2 = fmaf(w, ft.z, c2);
            T *= (1.f - al);          // transmittance only decays through valid fragments
        }
    }
    out[ob          ] = c0;
    out[ob +     HW_] = c1;
    out[ob + 2 * HW_] = c2;
}

extern "C" void kernel_launch(void* const* d_in, const int* in_sizes, int n_in,
                              void* d_out, int out_size) {
    const int*   frag  = (const int*)  d_in[0];  // int32 fragments
    const float* alpha = (const float*)d_in[1];
    const float* pt    = (const float*)d_in[2];
    const float* im    = (const float*)d_in[3];
    float*       out   = (float*)      d_out;

    prep_kernel<<<(P_ + 255) / 256, 256>>>(pt);

    dim3 grid(HW_ / 256, B_);   // 307200 % 256 == 0
    composite_kernel<<<grid, 256>>>(frag, alpha, im, out);
}